// round 6
// baseline (speedup 1.0000x reference)
#include <cuda_runtime.h>
#include <cuda_bf16.h>

// RNN: B=8192, T=2048, I=2, H=20
//   h_{t+1} = tanh(x_t @ W_ih^T + b_ih + b_hh + h_t @ W_hh^T)
//   out = h_T @ fc_w^T + fc_b ; h_state = h_T
//
// R6 design: 4 threads/row, 5 outputs each, and TWO rows per thread sharing
// the same in-register W_hh slice (100 regs used once, two independent
// recurrence chains through it). The kernel is latency-bound (occ ~9%,
// 7 warps/SM max from B=8192), so per-warp ILP is the only lever: two
// interleaved chains double the coverable work per warp.
// h exchanged via warp-local smem (double-buffered, one __syncwarp/step);
// LDS.128 returns h pre-packed as (h_2k,h_2k+1) pairs for fma.rn.f32x2.

#define BB 8192
#define TT 2048
#define HH 20
#define TPR 4    // threads per row
#define JPT 5    // hidden units per thread
#define RPT 2    // rows per thread
#define GPW 8    // groups (of 4 lanes) per warp
#define RPW (GPW * RPT)   // 16 rows per warp/CTA

typedef unsigned long long u64;

__device__ __forceinline__ u64 pack2(float lo, float hi) {
    u64 r; asm("mov.b64 %0, {%1, %2};" : "=l"(r) : "f"(lo), "f"(hi)); return r;
}
__device__ __forceinline__ float2 unpack2(u64 v) {
    float2 f; asm("mov.b64 {%0, %1}, %2;" : "=f"(f.x), "=f"(f.y) : "l"(v)); return f;
}
__device__ __forceinline__ u64 fma2(u64 a, u64 b, u64 c) {
    u64 d;
    asm("fma.rn.f32x2 %0, %1, %2, %3;" : "=l"(d) : "l"(a), "l"(b), "l"(c));
    return d;
}
__device__ __forceinline__ float tanh_fast(float a) {
    // tanh(a) = 1 - 2/(e+1), e = 2^(2a*log2e). |a| <= ~8 here -> no clamp.
    float e, r;
    asm("ex2.approx.f32 %0, %1;" : "=f"(e) : "f"(a * 2.8853900817779268f));
    asm("rcp.approx.f32 %0, %1;" : "=f"(r) : "f"(e + 1.0f));
    return fmaf(-2.0f, r, 1.0f);
}

__global__ __launch_bounds__(32)
void rnn_fused_kernel(const float* __restrict__ x,
                      const float* __restrict__ Wih,
                      const float* __restrict__ Whh,
                      const float* __restrict__ bih,
                      const float* __restrict__ bhh,
                      const float* __restrict__ fcw,
                      const float* __restrict__ fcb,
                      float* __restrict__ out) {
    __shared__ float hbuf[2][RPW][HH];   // stride-20-word rows

    const int part = (int)(threadIdx.x & 3u);  // which 5-unit slice
    const int grp  = (int)(threadIdx.x >> 2);  // group within warp (0..7)
    const unsigned gbase = threadIdx.x & ~3u;  // base lane of 4-lane group
    const unsigned FULL = 0xFFFFFFFFu;

    // two batch rows per thread (adjacent), sharing W registers
    const int r0 = (blockIdx.x * GPW + grp) * RPT;   // global row of chain 0
    const int s0 = grp * RPT;                        // smem row slot of chain 0

    // ---- per-thread constants, packed along k for f32x2 ----
    u64 W2[JPT][HH / 2];   // (W[j][2k], W[j][2k+1]) pairs: 50 u64
    u64 w01[JPT], bias2[JPT];
#pragma unroll
    for (int jj = 0; jj < JPT; ++jj) {
        const int j = part * JPT + jj;
        bias2[jj] = pack2(bih[j] + bhh[j], 0.0f);
        w01[jj]   = pack2(Wih[2 * j], Wih[2 * j + 1]);
#pragma unroll
        for (int kk = 0; kk < HH / 2; ++kk)
            W2[jj][kk] = pack2(Whh[j * HH + 2 * kk], Whh[j * HH + 2 * kk + 1]);
    }

    // h0 = 0 in buffer 0 (both rows)
#pragma unroll
    for (int rr = 0; rr < RPT; ++rr)
#pragma unroll
        for (int jj = 0; jj < JPT; ++jj)
            hbuf[0][s0 + rr][part * JPT + jj] = 0.0f;
    __syncwarp();

    // x: [B, T, 2] as one u64 (packed float2) per (row, t).
    // Lane `part` of the group holds steps 4c+part; shfl broadcasts.
    const u64* xr0 = reinterpret_cast<const u64*>(x) + (size_t)r0 * TT;
    const u64* xr1 = xr0 + TT;
    u64 xb0 = xr0[part];
    u64 xb1 = xr1[part];
    const int NC = TT / 4;

    float h[RPT][JPT];

    for (int c = 0; c < NC; ++c) {
        // branch-free prefetch (last iter re-reads chunk 0: in-bounds, unused)
        const int cn = (c + 1 < NC) ? (c + 1) : 0;
        const u64 xn0 = xr0[cn * 4 + part];
        const u64 xn1 = xr1[cn * 4 + part];

#pragma unroll
        for (int s = 0; s < 4; ++s) {
            const int rb = s & 1;          // read buffer
            const u64 xp0 = __shfl_sync(FULL, xb0, gbase + s);
            const u64 xp1 = __shfl_sync(FULL, xb1, gbase + s);

            // previous-step h for both rows, packed pairs via LDS.128
            u64 hpair[RPT][HH / 2];
#pragma unroll
            for (int rr = 0; rr < RPT; ++rr) {
                const ulonglong2* hp =
                    reinterpret_cast<const ulonglong2*>(hbuf[rb][s0 + rr]);
#pragma unroll
                for (int q = 0; q < 5; ++q) {
                    const ulonglong2 v = hp[q];
                    hpair[rr][2 * q]     = v.x;
                    hpair[rr][2 * q + 1] = v.y;
                }
            }

            // two independent 5x20 MACs through the shared W registers
#pragma unroll
            for (int jj = 0; jj < JPT; ++jj) {
                u64 acc0 = fma2(xp0, w01[jj], bias2[jj]);
                u64 acc1 = fma2(xp1, w01[jj], bias2[jj]);
#pragma unroll
                for (int kk = 0; kk < HH / 2; ++kk) {
                    acc0 = fma2(hpair[0][kk], W2[jj][kk], acc0);
                    acc1 = fma2(hpair[1][kk], W2[jj][kk], acc1);
                }
                const float2 f0 = unpack2(acc0);
                const float2 f1 = unpack2(acc1);
                h[0][jj] = tanh_fast(f0.x + f0.y);
                h[1][jj] = tanh_fast(f1.x + f1.y);
            }

#pragma unroll
            for (int rr = 0; rr < RPT; ++rr)
#pragma unroll
                for (int jj = 0; jj < JPT; ++jj)
                    hbuf[rb ^ 1][s0 + rr][part * JPT + jj] = h[rr][jj];
            __syncwarp();
        }
        xb0 = xn0;
        xb1 = xn1;
    }

    // ---- epilogue: fc head + h_state (both rows) ----
#pragma unroll
    for (int rr = 0; rr < RPT; ++rr) {
        float p = 0.0f;
#pragma unroll
        for (int jj = 0; jj < JPT; ++jj)
            p = fmaf(h[rr][jj], fcw[part * JPT + jj], p);
        p += __shfl_xor_sync(FULL, p, 1);
        p += __shfl_xor_sync(FULL, p, 2);
        if (part == 0) out[r0 + rr] = p + fcb[0];

        float* hs = out + BB;  // h_state [1, B, H] after out [B, 1]
#pragma unroll
        for (int jj = 0; jj < JPT; ++jj)
            hs[(size_t)(r0 + rr) * HH + part * JPT + jj] = h[rr][jj];
    }
}

extern "C" void kernel_launch(void* const* d_in, const int* in_sizes, int n_in,
                              void* d_out, int out_size) {
    const float* x   = (const float*)d_in[0];
    const float* Wih = (const float*)d_in[1];
    const float* Whh = (const float*)d_in[2];
    const float* bih = (const float*)d_in[3];
    const float* bhh = (const float*)d_in[4];
    const float* fcw = (const float*)d_in[5];
    const float* fcb = (const float*)d_in[6];
    float* out = (float*)d_out;

    const int nblocks = BB / RPW;              // 512 single-warp CTAs
    rnn_fused_kernel<<<nblocks, 32>>>(x, Wih, Whh, bih, bhh, fcw, fcb, out);
}